// round 1
// baseline (speedup 1.0000x reference)
#include <cuda_runtime.h>
#include <cuda_bf16.h>
#include <cstdint>

// EdgeDecoder:
//   P = z @ W1[0:64]   + b1     (per node, [N,64])
//   Q = z @ W1[64:128]          (per node, [N,64])
//   out[e] = relu(P[row[e]] + Q[col[e]]) . W2 + b2
//
// Phase 1: node GEMM  PQ[n, 0:64]=P, PQ[n,64:128]=Q   (51.2 MB, L2-resident)
// Phase 2: edge gather+reduce, half-warp (16 lanes) per edge.

#define HIDDEN 64
#define NMAX   100000

__device__ float g_PQ[(size_t)NMAX * 128];
__device__ int   g_idx_is64;

// ---------------------------------------------------------------------------
// Detect whether edge_index is int64 or int32 (JAX x64 ambiguity).
// Node indices are < n_nodes. If the buffer is actually int32 pairs, reading
// as int64 gives lo + hi*2^32 with hi a node index (almost surely nonzero)
// -> value far outside [0, n_nodes).
// ---------------------------------------------------------------------------
__global__ void detect_idx_kernel(const long long* __restrict__ ei,
                                  int n_check, long long n_nodes) {
    __shared__ int bad;
    if (threadIdx.x == 0) bad = 0;
    __syncthreads();
    for (int i = threadIdx.x; i < n_check; i += blockDim.x) {
        long long v = ei[i];
        if (v < 0 || v >= n_nodes) bad = 1;   // benign race, write of 1 only
    }
    __syncthreads();
    if (threadIdx.x == 0) g_idx_is64 = bad ? 0 : 1;
}

// ---------------------------------------------------------------------------
// Node GEMM: PQ[M,128] = z[M,64] @ Wcat[64,128] (+ b1 on first 64 cols)
//   Wcat[k][c] = (c < 64) ? W1[k][c] : W1[64+k][c-64]
// Block: 128 rows x 128 cols, 256 threads, 8x8 micro-tile, BK=32.
// ---------------------------------------------------------------------------
#define BM 128
#define BK 32

__global__ void __launch_bounds__(256, 2)
node_gemm_kernel(const float* __restrict__ z,
                 const float* __restrict__ W1,
                 const float* __restrict__ b1,
                 int M) {
    __shared__ float zs[BM][BK];     // 16 KB
    __shared__ float ws[BK][128];    // 16 KB

    const int tid = threadIdx.x;
    const int tx  = tid & 15;        // 16 col-groups
    const int ty  = tid >> 4;        // 16 row-groups
    const int row0 = blockIdx.x * BM;

    float acc[8][8];
#pragma unroll
    for (int r = 0; r < 8; r++)
#pragma unroll
        for (int j = 0; j < 8; j++) acc[r][j] = 0.f;

    for (int k0 = 0; k0 < HIDDEN; k0 += BK) {
        // ---- load z tile: 128 rows x 32 cols = 1024 float4, 4 per thread
#pragma unroll
        for (int i = 0; i < 4; i++) {
            int idx = tid + i * 256;         // float4 index
            int r   = idx >> 3;              // 8 float4 per row
            int c4  = idx & 7;
            float4 v = make_float4(0.f, 0.f, 0.f, 0.f);
            int grow = row0 + r;
            if (grow < M)
                v = *reinterpret_cast<const float4*>(z + (size_t)grow * HIDDEN + k0 + c4 * 4);
            *reinterpret_cast<float4*>(&zs[r][c4 * 4]) = v;
        }
        // ---- load W tile: 32 k x 128 c = 1024 float4, 4 per thread
#pragma unroll
        for (int i = 0; i < 4; i++) {
            int idx = tid + i * 256;
            int kk  = idx >> 5;              // 32 float4 per k-row
            int c4  = idx & 31;
            int c   = c4 * 4;
            int k   = k0 + kk;
            const float* src = (c < 64)
                ? (W1 + (size_t)k * HIDDEN + c)
                : (W1 + (size_t)(64 + k) * HIDDEN + (c - 64));
            *reinterpret_cast<float4*>(&ws[kk][c]) =
                *reinterpret_cast<const float4*>(src);
        }
        __syncthreads();

#pragma unroll 4
        for (int kk = 0; kk < BK; kk++) {
            float zr[8];
#pragma unroll
            for (int r = 0; r < 8; r++) zr[r] = zs[ty * 8 + r][kk];
            float4 wa = *reinterpret_cast<float4*>(&ws[kk][tx * 4]);
            float4 wb = *reinterpret_cast<float4*>(&ws[kk][64 + tx * 4]);
            float w[8] = {wa.x, wa.y, wa.z, wa.w, wb.x, wb.y, wb.z, wb.w};
#pragma unroll
            for (int r = 0; r < 8; r++)
#pragma unroll
                for (int j = 0; j < 8; j++)
                    acc[r][j] = fmaf(zr[r], w[j], acc[r][j]);
        }
        __syncthreads();
    }

    // ---- epilogue: bias on first 64 cols, store PQ
    float4 bv = __ldg(reinterpret_cast<const float4*>(b1) + tx);
#pragma unroll
    for (int r = 0; r < 8; r++) {
        int row = row0 + ty * 8 + r;
        if (row >= M) continue;
        float4 o1 = make_float4(acc[r][0] + bv.x, acc[r][1] + bv.y,
                                acc[r][2] + bv.z, acc[r][3] + bv.w);
        float4 o2 = make_float4(acc[r][4], acc[r][5], acc[r][6], acc[r][7]);
        float* dst = g_PQ + (size_t)row * 128;
        *reinterpret_cast<float4*>(dst + tx * 4)      = o1;
        *reinterpret_cast<float4*>(dst + 64 + tx * 4) = o2;
    }
}

// ---------------------------------------------------------------------------
// Edge pass: half-warp (16 lanes) per edge.
//   lane sub loads P[row][sub*4..+3], Q[col][sub*4..+3], W2[sub*4..+3]
//   s = sum relu(p+q)*w ; reduce over 16 lanes ; lane 0 stores out[e].
// ---------------------------------------------------------------------------
__global__ void __launch_bounds__(256)
edge_kernel(const void* __restrict__ ei_raw,
            const float* __restrict__ W2,
            const float* __restrict__ b2,
            float* __restrict__ out,
            int E) {
    const int t = blockIdx.x * blockDim.x + threadIdx.x;
    const int e = t >> 4;
    if (e >= E) return;
    const int sub = t & 15;

    int r, c;
    if (g_idx_is64) {
        const long long* ei = reinterpret_cast<const long long*>(ei_raw);
        r = (int)ei[e];
        c = (int)ei[(size_t)E + e];
    } else {
        const int* ei = reinterpret_cast<const int*>(ei_raw);
        r = ei[e];
        c = ei[(size_t)E + e];
    }

    const float4 p = *reinterpret_cast<const float4*>(g_PQ + (size_t)r * 128 + sub * 4);
    const float4 q = *reinterpret_cast<const float4*>(g_PQ + (size_t)c * 128 + 64 + sub * 4);
    const float4 w = __ldg(reinterpret_cast<const float4*>(W2) + sub);

    float s = fmaxf(p.x + q.x, 0.f) * w.x
            + fmaxf(p.y + q.y, 0.f) * w.y
            + fmaxf(p.z + q.z, 0.f) * w.z
            + fmaxf(p.w + q.w, 0.f) * w.w;

    s += __shfl_down_sync(0xffffffffu, s, 8, 16);
    s += __shfl_down_sync(0xffffffffu, s, 4, 16);
    s += __shfl_down_sync(0xffffffffu, s, 2, 16);
    s += __shfl_down_sync(0xffffffffu, s, 1, 16);

    if (sub == 0) out[e] = s + __ldg(b2);
}

// ---------------------------------------------------------------------------
extern "C" void kernel_launch(void* const* d_in, const int* in_sizes, int n_in,
                              void* d_out, int out_size) {
    const float* z  = (const float*)d_in[0];   // [N, 64]
    const void*  ei = d_in[1];                 // [2, E] int64 or int32
    const float* W1 = (const float*)d_in[2];   // [128, 64]
    const float* b1 = (const float*)d_in[3];   // [64]
    const float* W2 = (const float*)d_in[4];   // [64, 1]
    const float* b2 = (const float*)d_in[5];   // [1]
    float* out = (float*)d_out;                // [E, 1]

    const int M = in_sizes[0] / HIDDEN;        // 100000 nodes
    const int E = in_sizes[1] / 2;             // 3200000 edges

    // 1. detect index width
    int n_check = E < 4096 ? E : 4096;
    detect_idx_kernel<<<1, 256>>>((const long long*)ei, n_check, (long long)M);

    // 2. node-level GEMM -> PQ
    int gemm_blocks = (M + BM - 1) / BM;
    node_gemm_kernel<<<gemm_blocks, 256>>>(z, W1, b1, M);

    // 3. edge gather + reduce
    long long total_threads = (long long)E * 16;
    int edge_blocks = (int)((total_threads + 255) / 256);
    edge_kernel<<<edge_blocks, 256>>>(ei, W2, b2, out, E);
}

// round 3
// speedup vs baseline: 1.6383x; 1.6383x over previous
#include <cuda_runtime.h>
#include <cuda_fp16.h>
#include <cstdint>

// EdgeDecoder:
//   P = z @ W1[0:64]   + b1     (per node, [N,64])
//   Q = z @ W1[64:128]          (per node, [N,64])
//   out[e] = relu(P[row[e]] + Q[col[e]]) . W2 + b2
//
// Phase 1: node GEMM -> PQ table in FP16 (25.6 MB, L2-resident).
//          (index-width detection folded into block 0 of this kernel)
// Phase 2: edge gather+reduce, 8 lanes per edge, half2 math.

#define HIDDEN 64
#define NMAX   100000

__device__ __half g_PQh[(size_t)NMAX * 128];   // [node][0:64]=P, [64:128]=Q
__device__ int    g_idx_is64;

// ---------------------------------------------------------------------------
// Node GEMM: PQ[M,128] = z[M,64] @ Wcat[64,128] (+ b1 on first 64 cols)
//   Wcat[k][c] = (c < 64) ? W1[k][c] : W1[64+k][c-64]
// Block: 128 rows x 128 cols, 256 threads, 8x8 micro-tile, BK=32.
// Output stored as fp16. Block 0 additionally detects int32-vs-int64 edges.
// ---------------------------------------------------------------------------
#define BM 128
#define BK 32

__global__ void __launch_bounds__(256, 2)
node_gemm_kernel(const float* __restrict__ z,
                 const float* __restrict__ W1,
                 const float* __restrict__ b1,
                 const long long* __restrict__ ei,   // for idx-width detect
                 int n_check, int M) {
    // ---- index-width detection (block 0 only)
    if (blockIdx.x == 0) {
        __shared__ int bad;
        if (threadIdx.x == 0) bad = 0;
        __syncthreads();
        for (int i = threadIdx.x; i < n_check; i += blockDim.x) {
            long long v = ei[i];
            if (v < 0 || v >= (long long)M) bad = 1;   // benign race
        }
        __syncthreads();
        if (threadIdx.x == 0) g_idx_is64 = bad ? 0 : 1;
    }

    __shared__ float zs[BM][BK];     // 16 KB
    __shared__ float ws[BK][128];    // 16 KB

    const int tid = threadIdx.x;
    const int tx  = tid & 15;        // 16 col-groups
    const int ty  = tid >> 4;        // 16 row-groups
    const int row0 = blockIdx.x * BM;

    float acc[8][8];
#pragma unroll
    for (int r = 0; r < 8; r++)
#pragma unroll
        for (int j = 0; j < 8; j++) acc[r][j] = 0.f;

    for (int k0 = 0; k0 < HIDDEN; k0 += BK) {
        // ---- load z tile: 128 rows x 32 cols = 1024 float4, 4 per thread
#pragma unroll
        for (int i = 0; i < 4; i++) {
            int idx = tid + i * 256;         // float4 index
            int r   = idx >> 3;              // 8 float4 per row
            int c4  = idx & 7;
            float4 v = make_float4(0.f, 0.f, 0.f, 0.f);
            int grow = row0 + r;
            if (grow < M)
                v = *reinterpret_cast<const float4*>(z + (size_t)grow * HIDDEN + k0 + c4 * 4);
            *reinterpret_cast<float4*>(&zs[r][c4 * 4]) = v;
        }
        // ---- load W tile: 32 k x 128 c = 1024 float4, 4 per thread
#pragma unroll
        for (int i = 0; i < 4; i++) {
            int idx = tid + i * 256;
            int kk  = idx >> 5;              // 32 float4 per k-row
            int c4  = idx & 31;
            int c   = c4 * 4;
            int k   = k0 + kk;
            const float* src = (c < 64)
                ? (W1 + (size_t)k * HIDDEN + c)
                : (W1 + (size_t)(64 + k) * HIDDEN + (c - 64));
            *reinterpret_cast<float4*>(&ws[kk][c]) =
                *reinterpret_cast<const float4*>(src);
        }
        __syncthreads();

#pragma unroll 4
        for (int kk = 0; kk < BK; kk++) {
            float zr[8];
#pragma unroll
            for (int r = 0; r < 8; r++) zr[r] = zs[ty * 8 + r][kk];
            float4 wa = *reinterpret_cast<float4*>(&ws[kk][tx * 4]);
            float4 wb = *reinterpret_cast<float4*>(&ws[kk][64 + tx * 4]);
            float w[8] = {wa.x, wa.y, wa.z, wa.w, wb.x, wb.y, wb.z, wb.w};
#pragma unroll
            for (int r = 0; r < 8; r++)
#pragma unroll
                for (int j = 0; j < 8; j++)
                    acc[r][j] = fmaf(zr[r], w[j], acc[r][j]);
        }
        __syncthreads();
    }

    // ---- epilogue: bias on first 64 cols, convert to fp16, store PQ
    float4 bv = __ldg(reinterpret_cast<const float4*>(b1) + tx);
#pragma unroll
    for (int r = 0; r < 8; r++) {
        int row = row0 + ty * 8 + r;
        if (row >= M) continue;
        __half2 pbuf[2], qbuf[2];
        pbuf[0] = __floats2half2_rn(acc[r][0] + bv.x, acc[r][1] + bv.y);
        pbuf[1] = __floats2half2_rn(acc[r][2] + bv.z, acc[r][3] + bv.w);
        qbuf[0] = __floats2half2_rn(acc[r][4], acc[r][5]);
        qbuf[1] = __floats2half2_rn(acc[r][6], acc[r][7]);
        __half* dst = g_PQh + (size_t)row * 128;
        *reinterpret_cast<uint2*>(dst + tx * 4) =
            *reinterpret_cast<const uint2*>(pbuf);
        *reinterpret_cast<uint2*>(dst + 64 + tx * 4) =
            *reinterpret_cast<const uint2*>(qbuf);
    }
}

// ---------------------------------------------------------------------------
// Edge pass: 8 lanes per edge.
//   lane sub loads P[row][sub*8..+7] and Q[col][sub*8..+7] (fp16, 16 B each),
//   s = sum relu(p+q)*w (fp32 accum), reduce over 8 lanes, lane 0 stores.
// ---------------------------------------------------------------------------
__global__ void __launch_bounds__(256)
edge_kernel(const void* __restrict__ ei_raw,
            const float* __restrict__ W2,
            const float* __restrict__ b2,
            float* __restrict__ out,
            int E) {
    const int t = blockIdx.x * blockDim.x + threadIdx.x;
    const int e = t >> 3;
    if (e >= E) return;
    const int sub = t & 7;

    int r, c;
    if (g_idx_is64) {
        const long long* ei = reinterpret_cast<const long long*>(ei_raw);
        r = (int)ei[e];
        c = (int)ei[(size_t)E + e];
    } else {
        const int* ei = reinterpret_cast<const int*>(ei_raw);
        r = ei[e];
        c = ei[(size_t)E + e];
    }

    // 16 B of P row and 16 B of Q row per lane (8 halves each)
    const uint4 pv = *reinterpret_cast<const uint4*>(g_PQh + (size_t)r * 128 + sub * 8);
    const uint4 qv = *reinterpret_cast<const uint4*>(g_PQh + (size_t)c * 128 + 64 + sub * 8);

    const float4 w0 = __ldg(reinterpret_cast<const float4*>(W2) + sub * 2);
    const float4 w1 = __ldg(reinterpret_cast<const float4*>(W2) + sub * 2 + 1);
    const float wf[8] = {w0.x, w0.y, w0.z, w0.w, w1.x, w1.y, w1.z, w1.w};

    const __half2* ph = reinterpret_cast<const __half2*>(&pv);
    const __half2* qh = reinterpret_cast<const __half2*>(&qv);
    const __half2 zero = __float2half2_rn(0.f);

    float s = 0.f;
#pragma unroll
    for (int i = 0; i < 4; i++) {
        __half2 h = __hmax2(__hadd2(ph[i], qh[i]), zero);
        float2 f = __half22float2(h);
        s = fmaf(f.x, wf[2 * i], s);
        s = fmaf(f.y, wf[2 * i + 1], s);
    }

    s += __shfl_down_sync(0xffffffffu, s, 4, 8);
    s += __shfl_down_sync(0xffffffffu, s, 2, 8);
    s += __shfl_down_sync(0xffffffffu, s, 1, 8);

    if (sub == 0) out[e] = s + __ldg(b2);
}

// ---------------------------------------------------------------------------
extern "C" void kernel_launch(void* const* d_in, const int* in_sizes, int n_in,
                              void* d_out, int out_size) {
    const float* z  = (const float*)d_in[0];   // [N, 64]
    const void*  ei = d_in[1];                 // [2, E] int64 or int32
    const float* W1 = (const float*)d_in[2];   // [128, 64]
    const float* b1 = (const float*)d_in[3];   // [64]
    const float* W2 = (const float*)d_in[4];   // [64, 1]
    const float* b2 = (const float*)d_in[5];   // [1]
    float* out = (float*)d_out;                // [E, 1]

    const int M = in_sizes[0] / HIDDEN;        // 100000 nodes
    const int E = in_sizes[1] / 2;             // 3200000 edges

    // 1. node-level GEMM -> fp16 PQ (+ index-width detection in block 0)
    int n_check = E < 2048 ? E : 2048;
    int gemm_blocks = (M + BM - 1) / BM;
    node_gemm_kernel<<<gemm_blocks, 256>>>(z, W1, b1,
                                           (const long long*)ei, n_check, M);

    // 2. edge gather + reduce (8 lanes/edge)
    long long total_threads = (long long)E * 8;
    int edge_blocks = (int)((total_threads + 255) / 256);
    edge_kernel<<<edge_blocks, 256>>>(ei, W2, b2, out, E);
}

// round 4
// speedup vs baseline: 1.7375x; 1.0605x over previous
#include <cuda_runtime.h>
#include <cuda_fp16.h>
#include <cstdint>

// EdgeDecoder:
//   out[e] = relu(P[row]+Q[col]) . W2 + b2
// Algebraic fold: |w2_j| scaled into P,Q columns at GEMM time;
//   out[e] = sum_j sign_j * relu(P'[row][j] + Q'[col][j]) + b2
// Phase 1: node GEMM -> scaled fp16 PQ table (25.6 MB, L2-resident)
// Phase 2: edge gather + signed reduce, 8 lanes/edge. No W2 loads.

#define HIDDEN 64
#define NMAX   100000

__device__ __half    g_PQh[(size_t)NMAX * 128];  // [node][0:64]=P', [64:128]=Q'
__device__ int       g_idx_is64;
__device__ uint32_t  g_sign[2];                  // bit j = 1 if W2[j] < 0

// ---------------------------------------------------------------------------
// Node GEMM: PQ[M,128] = z[M,64] @ Wcat[64,128] (+ b1 on first 64 cols),
// all columns scaled by |W2[j]| (j = c mod 64). Stored fp16.
// Block 0 also: int32/int64 index detect + sign-mask build.
// ---------------------------------------------------------------------------
#define BM 128
#define BK 32

__global__ void __launch_bounds__(256, 2)
node_gemm_kernel(const float* __restrict__ z,
                 const float* __restrict__ W1,
                 const float* __restrict__ b1,
                 const float* __restrict__ W2,
                 const long long* __restrict__ ei,   // for idx-width detect
                 int n_check, int M) {
    if (blockIdx.x == 0) {
        // ---- sign mask (warps 0,1 handle j = tid in [0,64))
        if (threadIdx.x < 64) {
            unsigned m = __ballot_sync(0xffffffffu, W2[threadIdx.x] < 0.f);
            if ((threadIdx.x & 31) == 0) g_sign[threadIdx.x >> 5] = m;
        }
        // ---- index-width detection
        __shared__ int bad;
        if (threadIdx.x == 0) bad = 0;
        __syncthreads();
        for (int i = threadIdx.x; i < n_check; i += blockDim.x) {
            long long v = ei[i];
            if (v < 0 || v >= (long long)M) bad = 1;   // benign race
        }
        __syncthreads();
        if (threadIdx.x == 0) g_idx_is64 = bad ? 0 : 1;
    }

    __shared__ float zs[BM][BK];     // 16 KB
    __shared__ float ws[BK][128];    // 16 KB

    const int tid = threadIdx.x;
    const int tx  = tid & 15;        // 16 col-groups
    const int ty  = tid >> 4;        // 16 row-groups
    const int row0 = blockIdx.x * BM;

    float acc[8][8];
#pragma unroll
    for (int r = 0; r < 8; r++)
#pragma unroll
        for (int j = 0; j < 8; j++) acc[r][j] = 0.f;

    for (int k0 = 0; k0 < HIDDEN; k0 += BK) {
        // ---- load z tile: 128 rows x 32 cols
#pragma unroll
        for (int i = 0; i < 4; i++) {
            int idx = tid + i * 256;
            int r   = idx >> 3;
            int c4  = idx & 7;
            float4 v = make_float4(0.f, 0.f, 0.f, 0.f);
            int grow = row0 + r;
            if (grow < M)
                v = *reinterpret_cast<const float4*>(z + (size_t)grow * HIDDEN + k0 + c4 * 4);
            *reinterpret_cast<float4*>(&zs[r][c4 * 4]) = v;
        }
        // ---- load W tile scaled by |W2|: 32 k x 128 c
#pragma unroll
        for (int i = 0; i < 4; i++) {
            int idx = tid + i * 256;
            int kk  = idx >> 5;
            int c   = (idx & 31) * 4;
            int k   = k0 + kk;
            int j   = (c < 64) ? c : (c - 64);
            const float* src = (c < 64)
                ? (W1 + (size_t)k * HIDDEN + c)
                : (W1 + (size_t)(64 + k) * HIDDEN + j);
            float4 wv = *reinterpret_cast<const float4*>(src);
            float4 sv = __ldg(reinterpret_cast<const float4*>(W2 + j));
            wv.x *= fabsf(sv.x); wv.y *= fabsf(sv.y);
            wv.z *= fabsf(sv.z); wv.w *= fabsf(sv.w);
            *reinterpret_cast<float4*>(&ws[kk][c]) = wv;
        }
        __syncthreads();

#pragma unroll 4
        for (int kk = 0; kk < BK; kk++) {
            float zr[8];
#pragma unroll
            for (int r = 0; r < 8; r++) zr[r] = zs[ty * 8 + r][kk];
            float4 wa = *reinterpret_cast<float4*>(&ws[kk][tx * 4]);
            float4 wb = *reinterpret_cast<float4*>(&ws[kk][64 + tx * 4]);
            float w[8] = {wa.x, wa.y, wa.z, wa.w, wb.x, wb.y, wb.z, wb.w};
#pragma unroll
            for (int r = 0; r < 8; r++)
#pragma unroll
                for (int j = 0; j < 8; j++)
                    acc[r][j] = fmaf(zr[r], w[j], acc[r][j]);
        }
        __syncthreads();
    }

    // ---- epilogue: scaled bias on first 64 cols, fp16 store
    float4 bv = __ldg(reinterpret_cast<const float4*>(b1) + tx);
    float4 s2 = __ldg(reinterpret_cast<const float4*>(W2) + tx);
    bv.x *= fabsf(s2.x); bv.y *= fabsf(s2.y);
    bv.z *= fabsf(s2.z); bv.w *= fabsf(s2.w);
#pragma unroll
    for (int r = 0; r < 8; r++) {
        int row = row0 + ty * 8 + r;
        if (row >= M) continue;
        __half2 pbuf[2], qbuf[2];
        pbuf[0] = __floats2half2_rn(acc[r][0] + bv.x, acc[r][1] + bv.y);
        pbuf[1] = __floats2half2_rn(acc[r][2] + bv.z, acc[r][3] + bv.w);
        qbuf[0] = __floats2half2_rn(acc[r][4], acc[r][5]);
        qbuf[1] = __floats2half2_rn(acc[r][6], acc[r][7]);
        __half* dst = g_PQh + (size_t)row * 128;
        *reinterpret_cast<uint2*>(dst + tx * 4) =
            *reinterpret_cast<const uint2*>(pbuf);
        *reinterpret_cast<uint2*>(dst + 64 + tx * 4) =
            *reinterpret_cast<const uint2*>(qbuf);
    }
}

// ---------------------------------------------------------------------------
// Edge pass: 8 lanes per edge, no W2 loads.
//   lane sub: j = sub*8 + k, k in [0,8)
//   s = sum_k sign_j * relu(p_j + q_j)   (sign applied by fp32 sign-bit XOR)
// ---------------------------------------------------------------------------
__global__ void __launch_bounds__(256)
edge_kernel(const void* __restrict__ ei_raw,
            const float* __restrict__ b2,
            float* __restrict__ out,
            int E) {
    const int t = blockIdx.x * blockDim.x + threadIdx.x;
    const int e = t >> 3;
    if (e >= E) return;
    const int sub = t & 7;

    int r, c;
    if (g_idx_is64) {
        const long long* ei = reinterpret_cast<const long long*>(ei_raw);
        r = (int)ei[e];
        c = (int)ei[(size_t)E + e];
    } else {
        const int* ei = reinterpret_cast<const int*>(ei_raw);
        r = ei[e];
        c = ei[(size_t)E + e];
    }

    const uint4 pv = *reinterpret_cast<const uint4*>(g_PQh + (size_t)r * 128 + sub * 8);
    const uint4 qv = *reinterpret_cast<const uint4*>(g_PQh + (size_t)c * 128 + 64 + sub * 8);

    // sign byte for this lane's 8 columns (uniform broadcast load)
    const uint32_t bits = g_sign[sub >> 2];
    const uint32_t b8 = (bits >> ((sub & 3) * 8)) & 0xFFu;

    const __half2* ph = reinterpret_cast<const __half2*>(&pv);
    const __half2* qh = reinterpret_cast<const __half2*>(&qv);
    const __half2 zero = __float2half2_rn(0.f);

    float s = 0.f;
#pragma unroll
    for (int i = 0; i < 4; i++) {
        __half2 h = __hmax2(__hadd2(ph[i], qh[i]), zero);
        float2 f = __half22float2(h);
        uint32_t m0 = (b8 << (31 - 2 * i))     & 0x80000000u;
        uint32_t m1 = (b8 << (31 - 2 * i - 1)) & 0x80000000u;
        s += __uint_as_float(__float_as_uint(f.x) ^ m0);
        s += __uint_as_float(__float_as_uint(f.y) ^ m1);
    }

    s += __shfl_down_sync(0xffffffffu, s, 4, 8);
    s += __shfl_down_sync(0xffffffffu, s, 2, 8);
    s += __shfl_down_sync(0xffffffffu, s, 1, 8);

    if (sub == 0) out[e] = s + __ldg(b2);
}

// ---------------------------------------------------------------------------
extern "C" void kernel_launch(void* const* d_in, const int* in_sizes, int n_in,
                              void* d_out, int out_size) {
    const float* z  = (const float*)d_in[0];   // [N, 64]
    const void*  ei = d_in[1];                 // [2, E] int64 or int32
    const float* W1 = (const float*)d_in[2];   // [128, 64]
    const float* b1 = (const float*)d_in[3];   // [64]
    const float* W2 = (const float*)d_in[4];   // [64, 1]
    const float* b2 = (const float*)d_in[5];   // [1]
    float* out = (float*)d_out;                // [E, 1]

    const int M = in_sizes[0] / HIDDEN;        // 100000 nodes
    const int E = in_sizes[1] / 2;             // 3200000 edges

    int n_check = E < 2048 ? E : 2048;
    int gemm_blocks = (M + BM - 1) / BM;
    node_gemm_kernel<<<gemm_blocks, 256>>>(z, W1, b1, W2,
                                           (const long long*)ei, n_check, M);

    long long total_threads = (long long)E * 8;
    int edge_blocks = (int)((total_threads + 255) / 256);
    edge_kernel<<<edge_blocks, 256>>>(ei, b2, out, E);
}

// round 5
// speedup vs baseline: 2.0743x; 1.1939x over previous
#include <cuda_runtime.h>
#include <cuda_fp16.h>
#include <cstdint>

// EdgeDecoder:
//   out[e] = relu(P[row]+Q[col]) . W2 + b2
// |W2| folded into P,Q columns at GEMM time; edge pass applies only signs:
//   out[e] = sum_j sign_j * relu(P'[row][j] + Q'[col][j]) + b2
// Phase 1: node GEMM -> scaled fp16 PQ table (25.6 MB, L2-resident)
// Phase 2: edge gather + signed reduce, 8 lanes/edge, 2 edges/thread.

#define HIDDEN 64
#define NMAX   100000

__device__ __half    g_PQh[(size_t)NMAX * 128];  // [node][0:64]=P', [64:128]=Q'
__device__ int       g_idx_is64;
__device__ uint32_t  g_sign[2];                  // bit j = 1 if W2[j] < 0

// ---------------------------------------------------------------------------
// Node GEMM: PQ[M,128] = z[M,64] @ Wcat[64,128] (+ b1 on first 64 cols),
// all columns scaled by |W2[j]|. Stored fp16.
// Block 0 also: int32/int64 index detect + sign-mask build.
// ---------------------------------------------------------------------------
#define BM 128
#define BK 32

__global__ void __launch_bounds__(256, 2)
node_gemm_kernel(const float* __restrict__ z,
                 const float* __restrict__ W1,
                 const float* __restrict__ b1,
                 const float* __restrict__ W2,
                 const long long* __restrict__ ei,   // for idx-width detect
                 int n_check, int M) {
    if (blockIdx.x == 0) {
        if (threadIdx.x < 64) {
            unsigned m = __ballot_sync(0xffffffffu, W2[threadIdx.x] < 0.f);
            if ((threadIdx.x & 31) == 0) g_sign[threadIdx.x >> 5] = m;
        }
        __shared__ int bad;
        if (threadIdx.x == 0) bad = 0;
        __syncthreads();
        for (int i = threadIdx.x; i < n_check; i += blockDim.x) {
            long long v = ei[i];
            if (v < 0 || v >= (long long)M) bad = 1;   // benign race
        }
        __syncthreads();
        if (threadIdx.x == 0) g_idx_is64 = bad ? 0 : 1;
    }

    __shared__ float zs[BM][BK];     // 16 KB
    __shared__ float ws[BK][128];    // 16 KB

    const int tid = threadIdx.x;
    const int tx  = tid & 15;
    const int ty  = tid >> 4;
    const int row0 = blockIdx.x * BM;

    float acc[8][8];
#pragma unroll
    for (int r = 0; r < 8; r++)
#pragma unroll
        for (int j = 0; j < 8; j++) acc[r][j] = 0.f;

    for (int k0 = 0; k0 < HIDDEN; k0 += BK) {
#pragma unroll
        for (int i = 0; i < 4; i++) {
            int idx = tid + i * 256;
            int r   = idx >> 3;
            int c4  = idx & 7;
            float4 v = make_float4(0.f, 0.f, 0.f, 0.f);
            int grow = row0 + r;
            if (grow < M)
                v = *reinterpret_cast<const float4*>(z + (size_t)grow * HIDDEN + k0 + c4 * 4);
            *reinterpret_cast<float4*>(&zs[r][c4 * 4]) = v;
        }
#pragma unroll
        for (int i = 0; i < 4; i++) {
            int idx = tid + i * 256;
            int kk  = idx >> 5;
            int c   = (idx & 31) * 4;
            int k   = k0 + kk;
            int j   = (c < 64) ? c : (c - 64);
            const float* src = (c < 64)
                ? (W1 + (size_t)k * HIDDEN + c)
                : (W1 + (size_t)(64 + k) * HIDDEN + j);
            float4 wv = *reinterpret_cast<const float4*>(src);
            float4 sv = __ldg(reinterpret_cast<const float4*>(W2 + j));
            wv.x *= fabsf(sv.x); wv.y *= fabsf(sv.y);
            wv.z *= fabsf(sv.z); wv.w *= fabsf(sv.w);
            *reinterpret_cast<float4*>(&ws[kk][c]) = wv;
        }
        __syncthreads();

#pragma unroll 4
        for (int kk = 0; kk < BK; kk++) {
            float zr[8];
#pragma unroll
            for (int r = 0; r < 8; r++) zr[r] = zs[ty * 8 + r][kk];
            float4 wa = *reinterpret_cast<float4*>(&ws[kk][tx * 4]);
            float4 wb = *reinterpret_cast<float4*>(&ws[kk][64 + tx * 4]);
            float w[8] = {wa.x, wa.y, wa.z, wa.w, wb.x, wb.y, wb.z, wb.w};
#pragma unroll
            for (int r = 0; r < 8; r++)
#pragma unroll
                for (int j = 0; j < 8; j++)
                    acc[r][j] = fmaf(zr[r], w[j], acc[r][j]);
        }
        __syncthreads();
    }

    float4 bv = __ldg(reinterpret_cast<const float4*>(b1) + tx);
    float4 s2 = __ldg(reinterpret_cast<const float4*>(W2) + tx);
    bv.x *= fabsf(s2.x); bv.y *= fabsf(s2.y);
    bv.z *= fabsf(s2.z); bv.w *= fabsf(s2.w);
#pragma unroll
    for (int r = 0; r < 8; r++) {
        int row = row0 + ty * 8 + r;
        if (row >= M) continue;
        __half2 pbuf[2], qbuf[2];
        pbuf[0] = __floats2half2_rn(acc[r][0] + bv.x, acc[r][1] + bv.y);
        pbuf[1] = __floats2half2_rn(acc[r][2] + bv.z, acc[r][3] + bv.w);
        qbuf[0] = __floats2half2_rn(acc[r][4], acc[r][5]);
        qbuf[1] = __floats2half2_rn(acc[r][6], acc[r][7]);
        __half* dst = g_PQh + (size_t)row * 128;
        *reinterpret_cast<uint2*>(dst + tx * 4) =
            *reinterpret_cast<const uint2*>(pbuf);
        *reinterpret_cast<uint2*>(dst + 64 + tx * 4) =
            *reinterpret_cast<const uint2*>(qbuf);
    }
}

// ---------------------------------------------------------------------------
// Edge pass: 8 lanes/edge, 2 edges/thread (e and e+half).
// Per-thread setup (sign +-1.0f regs) amortizes over both edges; 4 gathers
// in flight per thread for MLP. Signs applied with FFMA.
// ---------------------------------------------------------------------------
__device__ __forceinline__ float edge_dot(const uint4& pv, const uint4& qv,
                                          const float* sgn) {
    const __half2* ph = reinterpret_cast<const __half2*>(&pv);
    const __half2* qh = reinterpret_cast<const __half2*>(&qv);
    const __half2 zero = __float2half2_rn(0.f);
    float s = 0.f;
#pragma unroll
    for (int i = 0; i < 4; i++) {
        __half2 h = __hmax2(__hadd2(ph[i], qh[i]), zero);
        float2 f = __half22float2(h);
        s = fmaf(f.x, sgn[2 * i], s);
        s = fmaf(f.y, sgn[2 * i + 1], s);
    }
    return s;
}

__global__ void __launch_bounds__(256)
edge_kernel(const void* __restrict__ ei_raw,
            const float* __restrict__ b2,
            float* __restrict__ out,
            int E, int half) {
    const int t = blockIdx.x * blockDim.x + threadIdx.x;
    const int e = t >> 3;
    if (e >= half) return;
    const int sub = t & 7;

    // per-thread sign constants (+-1.0f), derived once, used for both edges
    const uint32_t bits = g_sign[sub >> 2];
    const uint32_t b8 = (bits >> ((sub & 3) * 8)) & 0xFFu;
    float sgn[8];
#pragma unroll
    for (int k = 0; k < 8; k++)
        sgn[k] = ((b8 >> k) & 1u) ? -1.f : 1.f;

    const int  e2   = e + half;
    const bool has2 = (e2 < E);
    const int  e2s  = has2 ? e2 : e;   // safe address when no 2nd edge

    int r1, c1, r2, c2;
    if (g_idx_is64) {
        const long long* ei = reinterpret_cast<const long long*>(ei_raw);
        r1 = (int)ei[e];   c1 = (int)ei[(size_t)E + e];
        r2 = (int)ei[e2s]; c2 = (int)ei[(size_t)E + e2s];
    } else {
        const int* ei = reinterpret_cast<const int*>(ei_raw);
        r1 = ei[e];   c1 = ei[(size_t)E + e];
        r2 = ei[e2s]; c2 = ei[(size_t)E + e2s];
    }

    // 4 independent gathers in flight
    const uint4 p1 = __ldg(reinterpret_cast<const uint4*>(g_PQh + (size_t)r1 * 128 + sub * 8));
    const uint4 q1 = __ldg(reinterpret_cast<const uint4*>(g_PQh + (size_t)c1 * 128 + 64 + sub * 8));
    const uint4 p2 = __ldg(reinterpret_cast<const uint4*>(g_PQh + (size_t)r2 * 128 + sub * 8));
    const uint4 q2 = __ldg(reinterpret_cast<const uint4*>(g_PQh + (size_t)c2 * 128 + 64 + sub * 8));

    float s1 = edge_dot(p1, q1, sgn);
    float s2 = edge_dot(p2, q2, sgn);

    s1 += __shfl_down_sync(0xffffffffu, s1, 4, 8);
    s2 += __shfl_down_sync(0xffffffffu, s2, 4, 8);
    s1 += __shfl_down_sync(0xffffffffu, s1, 2, 8);
    s2 += __shfl_down_sync(0xffffffffu, s2, 2, 8);
    s1 += __shfl_down_sync(0xffffffffu, s1, 1, 8);
    s2 += __shfl_down_sync(0xffffffffu, s2, 1, 8);

    if (sub == 0) {
        const float bias = __ldg(b2);
        out[e] = s1 + bias;
        if (has2) out[e2] = s2 + bias;
    }
}

// ---------------------------------------------------------------------------
extern "C" void kernel_launch(void* const* d_in, const int* in_sizes, int n_in,
                              void* d_out, int out_size) {
    const float* z  = (const float*)d_in[0];   // [N, 64]
    const void*  ei = d_in[1];                 // [2, E] int64 or int32
    const float* W1 = (const float*)d_in[2];   // [128, 64]
    const float* b1 = (const float*)d_in[3];   // [64]
    const float* W2 = (const float*)d_in[4];   // [64, 1]
    const float* b2 = (const float*)d_in[5];   // [1]
    float* out = (float*)d_out;                // [E, 1]

    const int M = in_sizes[0] / HIDDEN;        // 100000 nodes
    const int E = in_sizes[1] / 2;             // 3200000 edges

    int n_check = E < 2048 ? E : 2048;
    int gemm_blocks = (M + BM - 1) / BM;
    node_gemm_kernel<<<gemm_blocks, 256>>>(z, W1, b1, W2,
                                           (const long long*)ei, n_check, M);

    const int half = (E + 1) / 2;
    long long total_threads = (long long)half * 8;
    int edge_blocks = (int)((total_threads + 255) / 256);
    edge_kernel<<<edge_blocks, 256>>>(ei, b2, out, E, half);
}

// round 6
// speedup vs baseline: 2.6299x; 1.2679x over previous
#include <cuda_runtime.h>
#include <cuda_fp16.h>
#include <cstdint>

// EdgeDecoder:
//   out[e] = relu(P[row]+Q[col]) . W2 + b2
// |W2| folded into PQ at epilogue; edge pass applies only signs.
// Phase 1: tensor-core node GEMM (mma.m16n8k16 f16 -> f32) -> fp16 PQ table.
// Phase 2: edge gather + signed reduce, 8 lanes/edge, 2 edges/thread.

#define HIDDEN 64
#define NMAX   100000

__device__ __half    g_PQh[(size_t)NMAX * 128];  // [node][0:64]=P', [64:128]=Q'
__device__ int       g_idx_is64;
__device__ uint32_t  g_sign[2];                  // bit j = 1 if W2[j] < 0

// ---------------------------------------------------------------------------
// m16n8k16 row.col f16.f16 -> f32 mma
// ---------------------------------------------------------------------------
__device__ __forceinline__ void mma16816(float* c,
                                         uint32_t a0, uint32_t a1,
                                         uint32_t a2, uint32_t a3,
                                         uint32_t b0, uint32_t b1) {
    asm volatile(
        "mma.sync.aligned.m16n8k16.row.col.f32.f16.f16.f32 "
        "{%0,%1,%2,%3}, {%4,%5,%6,%7}, {%8,%9}, {%0,%1,%2,%3};"
        : "+f"(c[0]), "+f"(c[1]), "+f"(c[2]), "+f"(c[3])
        : "r"(a0), "r"(a1), "r"(a2), "r"(a3), "r"(b0), "r"(b1));
}

// ---------------------------------------------------------------------------
// Node GEMM (tensor cores):
//   PQ[M,128] = fp16( (z[M,64] @ Wcat[64,128] + bias) * |W2| )
//   Wcat[k][c] = c<64 ? W1[k][c] : W1[64+k][c-64];  bias[c] = c<64 ? b1[c] : 0
// Block: 128 rows x 128 cols, 8 warps; warp = 16 rows x 128 cols
//   = 16 n8-tiles x 4 k-steps of m16n8k16.
// Smem rows padded to 72 halves -> conflict-free fragment LDS.
// Block 0 also: sign mask + int32/int64 index detection.
// ---------------------------------------------------------------------------
#define ZROW 72   // padded row stride (halves)

__global__ void __launch_bounds__(256, 2)
node_gemm_kernel(const float* __restrict__ z,
                 const float* __restrict__ W1,
                 const float* __restrict__ b1,
                 const float* __restrict__ W2,
                 const long long* __restrict__ ei,   // for idx-width detect
                 int n_check, int M) {
    __shared__ __half zh[128 * ZROW];     // 18 KB, z tile fp16
    __shared__ __half wt[128 * ZROW];     // 18 KB, W^T fp16: wt[c][k]
    __shared__ float  scale_s[128];
    __shared__ float  bias_s[128];

    const int tid  = threadIdx.x;
    const int lane = tid & 31;
    const int warp = tid >> 5;
    const int row0 = blockIdx.x * 128;

    if (blockIdx.x == 0) {
        if (tid < 64) {
            unsigned m = __ballot_sync(0xffffffffu, W2[tid] < 0.f);
            if ((tid & 31) == 0) g_sign[tid >> 5] = m;
        }
        __shared__ int bad;
        if (tid == 0) bad = 0;
        __syncthreads();
        for (int i = tid; i < n_check; i += blockDim.x) {
            long long v = ei[i];
            if (v < 0 || v >= (long long)M) bad = 1;   // benign race
        }
        __syncthreads();
        if (tid == 0) g_idx_is64 = bad ? 0 : 1;
    }

    // ---- per-column scale & bias
    if (tid < 128) {
        int j = tid & 63;
        scale_s[tid] = fabsf(__ldg(W2 + j));
        bias_s[tid]  = (tid < 64) ? __ldg(b1 + tid) : 0.f;
    }

    // ---- W^T fp16 tile: wt[c][k], from W1 [128][64] row-major
    for (int i = tid; i < 128 * 64; i += 256) {
        int kp = i >> 6;                   // W1 row 0..127
        int j  = i & 63;                   // W1 col
        int c  = (kp < 64) ? j : (j + 64);
        int k  = (kp < 64) ? kp : (kp - 64);
        wt[c * ZROW + k] = __float2half(W1[i]);
    }

    // ---- z tile fp16: zh[r][k], rows row0..row0+127
    for (int i = tid; i < 128 * 16; i += 256) {
        int r  = i >> 4;                   // 16 float4 per row
        int c4 = i & 15;
        float4 v = make_float4(0.f, 0.f, 0.f, 0.f);
        if (row0 + r < M)
            v = *reinterpret_cast<const float4*>(z + (size_t)(row0 + r) * 64 + c4 * 4);
        __half2 h0 = __floats2half2_rn(v.x, v.y);
        __half2 h1 = __floats2half2_rn(v.z, v.w);
        *reinterpret_cast<__half2*>(&zh[r * ZROW + c4 * 4])     = h0;
        *reinterpret_cast<__half2*>(&zh[r * ZROW + c4 * 4 + 2]) = h1;
    }
    __syncthreads();

    // ---- mma mainloop
    const int g  = lane >> 2;      // 0..7
    const int tg = lane & 3;       // 0..3
    const int mrow = warp * 16;

    float acc[16][4];
#pragma unroll
    for (int t = 0; t < 16; t++)
#pragma unroll
        for (int i = 0; i < 4; i++) acc[t][i] = 0.f;

#pragma unroll
    for (int ks = 0; ks < 4; ks++) {
        const int kb = ks * 16 + 2 * tg;
        uint32_t a0 = *reinterpret_cast<const uint32_t*>(&zh[(mrow + g) * ZROW + kb]);
        uint32_t a1 = *reinterpret_cast<const uint32_t*>(&zh[(mrow + g + 8) * ZROW + kb]);
        uint32_t a2 = *reinterpret_cast<const uint32_t*>(&zh[(mrow + g) * ZROW + kb + 8]);
        uint32_t a3 = *reinterpret_cast<const uint32_t*>(&zh[(mrow + g + 8) * ZROW + kb + 8]);
#pragma unroll
        for (int t = 0; t < 16; t++) {
            uint32_t b0 = *reinterpret_cast<const uint32_t*>(&wt[(t * 8 + g) * ZROW + kb]);
            uint32_t b1r = *reinterpret_cast<const uint32_t*>(&wt[(t * 8 + g) * ZROW + kb + 8]);
            mma16816(acc[t], a0, a1, a2, a3, b0, b1r);
        }
    }

    // ---- epilogue: (acc + bias) * |W2| -> fp16 PQ
    const int grow0 = row0 + mrow + g;
    const int grow1 = grow0 + 8;
#pragma unroll
    for (int t = 0; t < 16; t++) {
        int n = t * 8 + 2 * tg;
        float s0 = scale_s[n], s1 = scale_s[n + 1];
        float bb0 = bias_s[n], bb1 = bias_s[n + 1];
        if (grow0 < M) {
            __half2 h = __floats2half2_rn((acc[t][0] + bb0) * s0,
                                          (acc[t][1] + bb1) * s1);
            *reinterpret_cast<__half2*>(&g_PQh[(size_t)grow0 * 128 + n]) = h;
        }
        if (grow1 < M) {
            __half2 h = __floats2half2_rn((acc[t][2] + bb0) * s0,
                                          (acc[t][3] + bb1) * s1);
            *reinterpret_cast<__half2*>(&g_PQh[(size_t)grow1 * 128 + n]) = h;
        }
    }
}

// ---------------------------------------------------------------------------
// Edge pass: 8 lanes/edge, 2 edges/thread (e and e+half).
// ---------------------------------------------------------------------------
__device__ __forceinline__ float edge_dot(const uint4& pv, const uint4& qv,
                                          const float* sgn) {
    const __half2* ph = reinterpret_cast<const __half2*>(&pv);
    const __half2* qh = reinterpret_cast<const __half2*>(&qv);
    const __half2 zero = __float2half2_rn(0.f);
    float s = 0.f;
#pragma unroll
    for (int i = 0; i < 4; i++) {
        __half2 h = __hmax2(__hadd2(ph[i], qh[i]), zero);
        float2 f = __half22float2(h);
        s = fmaf(f.x, sgn[2 * i], s);
        s = fmaf(f.y, sgn[2 * i + 1], s);
    }
    return s;
}

__global__ void __launch_bounds__(256)
edge_kernel(const void* __restrict__ ei_raw,
            const float* __restrict__ b2,
            float* __restrict__ out,
            int E, int half) {
    const int t = blockIdx.x * blockDim.x + threadIdx.x;
    const int e = t >> 3;
    if (e >= half) return;
    const int sub = t & 7;

    const uint32_t bits = g_sign[sub >> 2];
    const uint32_t b8 = (bits >> ((sub & 3) * 8)) & 0xFFu;
    float sgn[8];
#pragma unroll
    for (int k = 0; k < 8; k++)
        sgn[k] = ((b8 >> k) & 1u) ? -1.f : 1.f;

    const int  e2   = e + half;
    const bool has2 = (e2 < E);
    const int  e2s  = has2 ? e2 : e;

    int r1, c1, r2, c2;
    if (g_idx_is64) {
        const long long* ei = reinterpret_cast<const long long*>(ei_raw);
        r1 = (int)ei[e];   c1 = (int)ei[(size_t)E + e];
        r2 = (int)ei[e2s]; c2 = (int)ei[(size_t)E + e2s];
    } else {
        const int* ei = reinterpret_cast<const int*>(ei_raw);
        r1 = ei[e];   c1 = ei[(size_t)E + e];
        r2 = ei[e2s]; c2 = ei[(size_t)E + e2s];
    }

    const uint4 p1 = __ldg(reinterpret_cast<const uint4*>(g_PQh + (size_t)r1 * 128 + sub * 8));
    const uint4 q1 = __ldg(reinterpret_cast<const uint4*>(g_PQh + (size_t)c1 * 128 + 64 + sub * 8));
    const uint4 p2 = __ldg(reinterpret_cast<const uint4*>(g_PQh + (size_t)r2 * 128 + sub * 8));
    const uint4 q2 = __ldg(reinterpret_cast<const uint4*>(g_PQh + (size_t)c2 * 128 + 64 + sub * 8));

    float s1 = edge_dot(p1, q1, sgn);
    float s2 = edge_dot(p2, q2, sgn);

    s1 += __shfl_down_sync(0xffffffffu, s1, 4, 8);
    s2 += __shfl_down_sync(0xffffffffu, s2, 4, 8);
    s1 += __shfl_down_sync(0xffffffffu, s1, 2, 8);
    s2 += __shfl_down_sync(0xffffffffu, s2, 2, 8);
    s1 += __shfl_down_sync(0xffffffffu, s1, 1, 8);
    s2 += __shfl_down_sync(0xffffffffu, s2, 1, 8);

    if (sub == 0) {
        const float bias = __ldg(b2);
        out[e] = s1 + bias;
        if (has2) out[e2] = s2 + bias;
    }
}

// ---------------------------------------------------------------------------
extern "C" void kernel_launch(void* const* d_in, const int* in_sizes, int n_in,
                              void* d_out, int out_size) {
    const float* z  = (const float*)d_in[0];   // [N, 64]
    const void*  ei = d_in[1];                 // [2, E] int64 or int32
    const float* W1 = (const float*)d_in[2];   // [128, 64]
    const float* b1 = (const float*)d_in[3];   // [64]
    const float* W2 = (const float*)d_in[4];   // [64, 1]
    const float* b2 = (const float*)d_in[5];   // [1]
    float* out = (float*)d_out;                // [E, 1]

    const int M = in_sizes[0] / HIDDEN;        // 100000 nodes
    const int E = in_sizes[1] / 2;             // 3200000 edges

    int n_check = E < 2048 ? E : 2048;
    int gemm_blocks = (M + 127) / 128;
    node_gemm_kernel<<<gemm_blocks, 256>>>(z, W1, b1, W2,
                                           (const long long*)ei, n_check, M);

    const int half = (E + 1) / 2;
    long long total_threads = (long long)half * 8;
    int edge_blocks = (int)((total_threads + 255) / 256);
    edge_kernel<<<edge_blocks, 256>>>(ei, b2, out, E, half);
}